// round 5
// baseline (speedup 1.0000x reference)
#include <cuda_runtime.h>
#include <math.h>

// Output: spikes[t, b, n] = (t == spike_time[b,n]) ? 1.f : 0.f
// spike_time = floor(sigmoid(x) * (T-1)) with XLA-bit-exact f32 sigmoid:
//   s = 1 / (1 + __nv_expf(-x)), every op f32-rounded (verified rel_err==0).
//
// R5: 8 columns per thread (two adjacent STG.128 per plane) -> 1KB contiguous
// per warp per plane visit, halving plane-hop frequency for better DRAM row
// locality. T-split 4 keeps grid at 2048 blocks (>= 8 resident blocks/SM).

extern "C" __device__ float __nv_expf(float);  // libdevice precise expf

__device__ __forceinline__ int xla_spike_time(float x, float tm1) {
    float e = __nv_expf(-x);                       // f32 exp(-x), libdevice
    float s = __fdiv_rn(1.0f, __fadd_rn(1.0f, e)); // 1/(1+e), f32 rn
    return (int)floorf(__fmul_rn(s, tm1));         // floor(s*(T-1))
}

template <int T, int TSPLIT>
__global__ void __launch_bounds__(256)
temporal_encode_fused8(const float4* __restrict__ in,
                       float4* __restrict__ out,
                       int BN8)  // B*N/8
{
    int idx = blockIdx.x * blockDim.x + threadIdx.x;
    if (idx >= BN8) return;

    // Two adjacent float4 columns per thread (8 floats).
    float4 xa = in[idx * 2 + 0];
    float4 xb = in[idx * 2 + 1];

    const float tm1 = (float)(T - 1);
    int st0 = xla_spike_time(xa.x, tm1);
    int st1 = xla_spike_time(xa.y, tm1);
    int st2 = xla_spike_time(xa.z, tm1);
    int st3 = xla_spike_time(xa.w, tm1);
    int st4 = xla_spike_time(xb.x, tm1);
    int st5 = xla_spike_time(xb.y, tm1);
    int st6 = xla_spike_time(xb.z, tm1);
    int st7 = xla_spike_time(xb.w, tm1);

    constexpr int TCHUNK = T / TSPLIT;   // 25
    const int t0 = blockIdx.y * TCHUNK;

    const size_t stride4 = (size_t)BN8 * 2;  // float4 units == B*N floats
    float4* p = out + (size_t)t0 * stride4 + (size_t)idx * 2;
#pragma unroll
    for (int i = 0; i < TCHUNK; i++) {
        int t = t0 + i;
        float4 va, vb;
        va.x = (st0 == t) ? 1.0f : 0.0f;
        va.y = (st1 == t) ? 1.0f : 0.0f;
        va.z = (st2 == t) ? 1.0f : 0.0f;
        va.w = (st3 == t) ? 1.0f : 0.0f;
        vb.x = (st4 == t) ? 1.0f : 0.0f;
        vb.y = (st5 == t) ? 1.0f : 0.0f;
        vb.z = (st6 == t) ? 1.0f : 0.0f;
        vb.w = (st7 == t) ? 1.0f : 0.0f;
        __stcs(p + 0, va);     // streaming stores, evict-first
        __stcs(p + 1, vb);
        p += stride4;
    }
}

// Generic-T fallback (4 columns per thread, dynamic trip count)
__global__ void __launch_bounds__(256)
temporal_encode_fused_dyn(const float4* __restrict__ in,
                          float4* __restrict__ out,
                          int BN4, int T)
{
    int idx = blockIdx.x * blockDim.x + threadIdx.x;
    if (idx >= BN4) return;

    float4 x = in[idx];
    const float tm1 = (float)(T - 1);
    int st0 = xla_spike_time(x.x, tm1);
    int st1 = xla_spike_time(x.y, tm1);
    int st2 = xla_spike_time(x.z, tm1);
    int st3 = xla_spike_time(x.w, tm1);

    float4* p = out + idx;
    const size_t stride4 = (size_t)BN4;
#pragma unroll 4
    for (int t = 0; t < T; t++) {
        float4 v;
        v.x = (st0 == t) ? 1.0f : 0.0f;
        v.y = (st1 == t) ? 1.0f : 0.0f;
        v.z = (st2 == t) ? 1.0f : 0.0f;
        v.w = (st3 == t) ? 1.0f : 0.0f;
        __stcs(p, v);
        p += stride4;
    }
}

extern "C" void kernel_launch(void* const* d_in, const int* in_sizes, int n_in,
                              void* d_out, int out_size)
{
    const float* in = (const float*)d_in[0];
    float4* out = (float4*)d_out;

    const int BN = in_sizes[0];   // B * N = 1048576
    const int T = out_size / BN;  // timesteps = 100

    const int threads = 256;

    if (T == 100 && (BN % (8 * threads)) == 0) {
        const int BN8 = BN / 8;
        dim3 grid(BN8 / threads, 4);   // 512 x 4 = 2048 blocks, 25 planes each
        temporal_encode_fused8<100, 4><<<grid, threads>>>(
            (const float4*)in, out, BN8);
    } else {
        const int BN4 = BN / 4;
        const int cblocks = (BN4 + threads - 1) / threads;
        temporal_encode_fused_dyn<<<cblocks, threads>>>(
            (const float4*)in, out, BN4, T);
    }
}

// round 6
// speedup vs baseline: 1.7007x; 1.7007x over previous
#include <cuda_runtime.h>
#include <math.h>

// Output: spikes[t, b, n] = (t == spike_time[b,n]) ? 1.f : 0.f
// spike_time = floor(sigmoid(x) * (T-1)) with XLA-bit-exact f32 sigmoid:
//   s = 1 / (1 + __nv_expf(-x)), every op f32-rounded (verified rel_err==0).
//
// R6: 8 columns/thread with CORRECT coalescing (R5 interleaved lanes by
// accident -> L1-bound). Warp w owns 64 consecutive float4 columns; lane l
// writes [base+l] and [base+32+l]: two fully-coalesced 512B STG.128 bursts
// = 1KB contiguous per warp per plane. T-split 4 -> 2048 blocks.

extern "C" __device__ float __nv_expf(float);  // libdevice precise expf

__device__ __forceinline__ int xla_spike_time(float x, float tm1) {
    float e = __nv_expf(-x);                       // f32 exp(-x), libdevice
    float s = __fdiv_rn(1.0f, __fadd_rn(1.0f, e)); // 1/(1+e), f32 rn
    return (int)floorf(__fmul_rn(s, tm1));         // floor(s*(T-1))
}

template <int T, int TSPLIT>
__global__ void __launch_bounds__(256)
temporal_encode_fused8(const float4* __restrict__ in,
                       float4* __restrict__ out,
                       int BN4)  // B*N/4 (total float4 columns)
{
    const int lane = threadIdx.x & 31;
    const int warp = threadIdx.x >> 5;
    // Warp-contiguous mapping: each warp owns 64 consecutive float4 columns.
    const int base = blockIdx.x * (int)blockDim.x * 2 + warp * 64 + lane;
    if (base + 32 >= BN4 && base >= BN4) return;  // (shapes divide evenly here)

    float4 xa = in[base];
    float4 xb = in[base + 32];

    const float tm1 = (float)(T - 1);
    int st0 = xla_spike_time(xa.x, tm1);
    int st1 = xla_spike_time(xa.y, tm1);
    int st2 = xla_spike_time(xa.z, tm1);
    int st3 = xla_spike_time(xa.w, tm1);
    int st4 = xla_spike_time(xb.x, tm1);
    int st5 = xla_spike_time(xb.y, tm1);
    int st6 = xla_spike_time(xb.z, tm1);
    int st7 = xla_spike_time(xb.w, tm1);

    constexpr int TCHUNK = T / TSPLIT;   // 25
    const int t0 = blockIdx.y * TCHUNK;

    const size_t stride4 = (size_t)BN4;  // float4 units == B*N floats
    float4* p = out + (size_t)t0 * stride4 + base;
#pragma unroll
    for (int i = 0; i < TCHUNK; i++) {
        int t = t0 + i;
        float4 va, vb;
        va.x = (st0 == t) ? 1.0f : 0.0f;
        va.y = (st1 == t) ? 1.0f : 0.0f;
        va.z = (st2 == t) ? 1.0f : 0.0f;
        va.w = (st3 == t) ? 1.0f : 0.0f;
        vb.x = (st4 == t) ? 1.0f : 0.0f;
        vb.y = (st5 == t) ? 1.0f : 0.0f;
        vb.z = (st6 == t) ? 1.0f : 0.0f;
        vb.w = (st7 == t) ? 1.0f : 0.0f;
        __stcs(p, va);         // lanes contiguous: 512B warp burst
        __stcs(p + 32, vb);    // next 512B -> 1KB contiguous per warp
        p += stride4;
    }
}

// Generic-T fallback (4 columns per thread, dynamic trip count)
__global__ void __launch_bounds__(256)
temporal_encode_fused_dyn(const float4* __restrict__ in,
                          float4* __restrict__ out,
                          int BN4, int T)
{
    int idx = blockIdx.x * blockDim.x + threadIdx.x;
    if (idx >= BN4) return;

    float4 x = in[idx];
    const float tm1 = (float)(T - 1);
    int st0 = xla_spike_time(x.x, tm1);
    int st1 = xla_spike_time(x.y, tm1);
    int st2 = xla_spike_time(x.z, tm1);
    int st3 = xla_spike_time(x.w, tm1);

    float4* p = out + idx;
    const size_t stride4 = (size_t)BN4;
#pragma unroll 4
    for (int t = 0; t < T; t++) {
        float4 v;
        v.x = (st0 == t) ? 1.0f : 0.0f;
        v.y = (st1 == t) ? 1.0f : 0.0f;
        v.z = (st2 == t) ? 1.0f : 0.0f;
        v.w = (st3 == t) ? 1.0f : 0.0f;
        __stcs(p, v);
        p += stride4;
    }
}

extern "C" void kernel_launch(void* const* d_in, const int* in_sizes, int n_in,
                              void* d_out, int out_size)
{
    const float* in = (const float*)d_in[0];
    float4* out = (float4*)d_out;

    const int BN = in_sizes[0];   // B * N = 1048576
    const int T = out_size / BN;  // timesteps = 100

    const int threads = 256;

    if (T == 100 && (BN % (8 * threads)) == 0) {
        const int BN4 = BN / 4;
        dim3 grid(BN / (8 * threads), 4);  // 512 x 4 = 2048 blocks, 25 planes
        temporal_encode_fused8<100, 4><<<grid, threads>>>(
            (const float4*)in, out, BN4);
    } else {
        const int BN4 = BN / 4;
        const int cblocks = (BN4 + threads - 1) / threads;
        temporal_encode_fused_dyn<<<cblocks, threads>>>(
            (const float4*)in, out, BN4, T);
    }
}

// round 7
// speedup vs baseline: 1.7805x; 1.0469x over previous
#include <cuda_runtime.h>
#include <math.h>

// Output: spikes[t, b, n] = (t == spike_time[b,n]) ? 1.f : 0.f
// spike_time = floor(sigmoid(x) * (T-1)) with XLA-bit-exact f32 sigmoid:
//   s = 1 / (1 + __nv_expf(-x)), every op f32-rounded (verified rel_err==0).
//
// R7: R4 shape (4 cols/thread, perfectly coalesced 512B warp bursts) with
// TSPLIT=10: grid (1024, 10) = 10240 blocks, 10 planes each. Finer wave
// granularity -> higher occupancy, smaller drain tail. Input re-reads hit
// L2 (4MB input fully resident), so no extra DRAM traffic.

extern "C" __device__ float __nv_expf(float);  // libdevice precise expf

__device__ __forceinline__ int xla_spike_time(float x, float tm1) {
    float e = __nv_expf(-x);                       // f32 exp(-x), libdevice
    float s = __fdiv_rn(1.0f, __fadd_rn(1.0f, e)); // 1/(1+e), f32 rn
    return (int)floorf(__fmul_rn(s, tm1));         // floor(s*(T-1))
}

template <int T, int TSPLIT>
__global__ void __launch_bounds__(256)
temporal_encode_fused(const float4* __restrict__ in,
                      float4* __restrict__ out,
                      int BN4)  // B*N/4
{
    int idx = blockIdx.x * blockDim.x + threadIdx.x;
    if (idx >= BN4) return;

    float4 x = in[idx];
    const float tm1 = (float)(T - 1);
    int st0 = xla_spike_time(x.x, tm1);
    int st1 = xla_spike_time(x.y, tm1);
    int st2 = xla_spike_time(x.z, tm1);
    int st3 = xla_spike_time(x.w, tm1);

    constexpr int TCHUNK = T / TSPLIT;   // 10
    const int t0 = blockIdx.y * TCHUNK;

    const size_t stride4 = (size_t)BN4;  // float4 units == B*N floats
    float4* p = out + (size_t)t0 * stride4 + idx;
#pragma unroll
    for (int i = 0; i < TCHUNK; i++) {
        int t = t0 + i;
        float4 v;
        v.x = (st0 == t) ? 1.0f : 0.0f;
        v.y = (st1 == t) ? 1.0f : 0.0f;
        v.z = (st2 == t) ? 1.0f : 0.0f;
        v.w = (st3 == t) ? 1.0f : 0.0f;
        __stcs(p, v);          // streaming store, evict-first
        p += stride4;
    }
}

// Generic-T fallback (single split, dynamic trip count)
__global__ void __launch_bounds__(256)
temporal_encode_fused_dyn(const float4* __restrict__ in,
                          float4* __restrict__ out,
                          int BN4, int T)
{
    int idx = blockIdx.x * blockDim.x + threadIdx.x;
    if (idx >= BN4) return;

    float4 x = in[idx];
    const float tm1 = (float)(T - 1);
    int st0 = xla_spike_time(x.x, tm1);
    int st1 = xla_spike_time(x.y, tm1);
    int st2 = xla_spike_time(x.z, tm1);
    int st3 = xla_spike_time(x.w, tm1);

    float4* p = out + idx;
    const size_t stride4 = (size_t)BN4;
#pragma unroll 4
    for (int t = 0; t < T; t++) {
        float4 v;
        v.x = (st0 == t) ? 1.0f : 0.0f;
        v.y = (st1 == t) ? 1.0f : 0.0f;
        v.z = (st2 == t) ? 1.0f : 0.0f;
        v.w = (st3 == t) ? 1.0f : 0.0f;
        __stcs(p, v);
        p += stride4;
    }
}

extern "C" void kernel_launch(void* const* d_in, const int* in_sizes, int n_in,
                              void* d_out, int out_size)
{
    const float* in = (const float*)d_in[0];
    float4* out = (float4*)d_out;

    const int BN = in_sizes[0];   // B * N = 1048576
    const int T = out_size / BN;  // timesteps = 100
    const int BN4 = BN / 4;

    const int threads = 256;
    const int cblocks = (BN4 + threads - 1) / threads;

    if (T == 100) {
        dim3 grid(cblocks, 10);   // 1024 x 10 = 10240 blocks, 10 planes each
        temporal_encode_fused<100, 10><<<grid, threads>>>(
            (const float4*)in, out, BN4);
    } else {
        temporal_encode_fused_dyn<<<cblocks, threads>>>(
            (const float4*)in, out, BN4, T);
    }
}